// round 12
// baseline (speedup 1.0000x reference)
#include <cuda_runtime.h>
#include <cuda_bf16.h>
#include <cuda_fp16.h>
#include <cstdint>

// ---------------- problem constants ----------------
#define TB      64          // batch
#define NCH     512         // hidden cells
#define TSTEPS  1024        // SY*SX
#define G4      2048        // 4*NCH gate columns
#define K_IH    560         // 48 + NCH
#define NCTA    128         // CTA (j,s): j = col-block (64), s = batch half (2)
#define THREADS 256         // w0-3 seq (rg=w&1, kh=(w>>1)&1); w4-7 pre (same split)
#define HSTRIDE ((size_t)TSTEPS * NCH)  // out batch-row stride (flat [t][n] view)
#define S_W     264         // smem words/col, fp16 pairs (==8 mod 32 -> conflict-free LDS.64)
#define S_X     48          // xc_k smem words/col (bf16 quads, K=48)
#define FPAD    32          // ints per flag: one 128B line each
#define RSL     32          // CTA-private ring slots
// smem layout (words)
#define OFF_WPRE (32 * S_W)             // pre weights (W_ihh)
#define OFF_RED  (64 * S_W)             // seq kh1 partials: 64 thr * 20
#define OFF_RED2 (OFF_RED + 64 * 20)    // pre kh1 partials: 64 thr * 20
#define SMEM_WORDS (OFF_RED2 + 64 * 20)

// ---------------- device scratch (static: allocation-free) ----------------
__device__ float d_G[(size_t)TSTEPS * TB * G4];        // xc_k output (x@W_ihx + bias), 512 MB
__device__ uint4 d_Hq[(size_t)TSTEPS * TB * 128];      // h fp16 {hi2,hi2,lo2,lo2} per 4 cells, 128 MB
__device__ float d_R[(size_t)NCTA * RSL * 1024];       // CTA-private pre rings (32 rows x 32 cols)
__device__ int   d_h_done[NCTA * FPAD];

// ---------------- bf16 helpers (xc_k only) ----------------
__device__ __forceinline__ uint32_t pack2b(float e0, float e1) {
    uint32_t d;
    asm("cvt.rn.bf16x2.f32 %0, %1, %2;" : "=r"(d) : "f"(e1), "f"(e0));
    return d;
}
__device__ __forceinline__ uint32_t lo_resb(uint32_t hp, float e0, float e1) {
    float h0 = __uint_as_float(hp << 16);
    float h1 = __uint_as_float(hp & 0xFFFF0000u);
    return pack2b(e0 - h0, e1 - h1);
}
__device__ __forceinline__ void mma16b(float* c,
                                       uint32_t a0, uint32_t a1, uint32_t a2, uint32_t a3,
                                       uint32_t b0, uint32_t b1) {
    asm volatile(
        "mma.sync.aligned.m16n8k16.row.col.f32.bf16.bf16.f32 "
        "{%0,%1,%2,%3},{%4,%5,%6,%7},{%8,%9},{%0,%1,%2,%3};"
        : "+f"(c[0]), "+f"(c[1]), "+f"(c[2]), "+f"(c[3])
        : "r"(a0), "r"(a1), "r"(a2), "r"(a3), "r"(b0), "r"(b1));
}

// ---------------- fp16 helpers (main kernel) ----------------
__device__ __forceinline__ uint32_t pack2h(float e0, float e1) {
    uint32_t d;
    asm("cvt.rn.f16x2.f32 %0, %1, %2;" : "=r"(d) : "f"(e1), "f"(e0));
    return d;
}
__device__ __forceinline__ uint32_t lo_resh(uint32_t hp, float e0, float e1) {
    __half2 h = *reinterpret_cast<__half2*>(&hp);
    float h0 = __half2float(__low2half(h));
    float h1 = __half2float(__high2half(h));
    return pack2h(e0 - h0, e1 - h1);
}
__device__ __forceinline__ void mma16h(float* c,
                                       uint32_t a0, uint32_t a1, uint32_t a2, uint32_t a3,
                                       uint32_t b0, uint32_t b1) {
    asm volatile(
        "mma.sync.aligned.m16n8k16.row.col.f32.f16.f16.f32 "
        "{%0,%1,%2,%3},{%4,%5,%6,%7},{%8,%9},{%0,%1,%2,%3};"
        : "+f"(c[0]), "+f"(c[1]), "+f"(c[2]), "+f"(c[3])
        : "r"(a0), "r"(a1), "r"(a2), "r"(a3), "r"(b0), "r"(b1));
}

__device__ __forceinline__ int ld_acq(const int* p) {
    int v;
    asm volatile("ld.acquire.gpu.global.b32 %0, [%1];" : "=r"(v) : "l"(p) : "memory");
    return v;
}
__device__ __forceinline__ void st_rel(int* p, int v) {
    asm volatile("st.release.gpu.global.b32 [%0], %1;" :: "l"(p), "r"(v) : "memory");
}
__device__ __forceinline__ float sigm(float x)  { return 1.0f / (1.0f + __expf(-x)); }
__device__ __forceinline__ float tanh_f(float x){ return 1.0f - 2.0f / (__expf(2.0f * x) + 1.0f); }

// ---------------- init (graph-replay safe) ----------------
__global__ void init_k() {
    int i = blockIdx.x * blockDim.x + threadIdx.x;
    if (i < NCTA * FPAD) d_h_done[i] = -1;
}

// ---------------- Xc precompute: G0[t] = bias + x_t @ W_ih[:, :48]^T (bf16 3-pass) ----------------
__global__ void __launch_bounds__(128)
xc_k(const float* __restrict__ batch, const float* __restrict__ W_ih,
     const float* __restrict__ b_ih, const float* __restrict__ b_hh) {
    __shared__ uint32_t sw[32 * S_X];
    const int tid = threadIdx.x;
    const int lane = tid & 31, w = tid >> 5;
    const int gid = lane >> 2, tig = lane & 3;
    const int row0 = w * 16 + gid, row1 = row0 + 8;
    const int gb = blockIdx.x * 32;

    for (int idx = tid; idx < 32 * 24; idx += 128) {
        int cl = idx / 24, k0 = (idx - cl * 24) * 2;
        float w0 = W_ih[(size_t)(gb + cl) * K_IH + k0];
        float w1 = W_ih[(size_t)(gb + cl) * K_IH + k0 + 1];
        uint32_t hi = pack2b(w0, w1);
        int kt = k0 >> 4, r = k0 & 15;
        int pos = cl * S_X + kt * 16 + (r >> 2) * 4 + ((r >> 1) & 1);
        sw[pos] = hi; sw[pos + 2] = lo_resb(hi, w0, w1);
    }
    __syncthreads();

    float bias[4][2];
#pragma unroll
    for (int nt = 0; nt < 4; nt++) {
        int g = gb + nt * 8 + tig * 2;
        bias[nt][0] = b_ih[g] + b_hh[g];
        bias[nt][1] = b_ih[g + 1] + b_hh[g + 1];
    }

    for (int us = 0; us < 64; us++) {
        const int u = blockIdx.y * 64 + us;
        const int i = u >> 5, j = u & 31;
        float acc[4][4];
#pragma unroll
        for (int nt = 0; nt < 4; nt++) {
            acc[nt][0] = bias[nt][0]; acc[nt][1] = bias[nt][1];
            acc[nt][2] = bias[nt][0]; acc[nt][3] = bias[nt][1];
        }
#pragma unroll
        for (int kt = 0; kt < 3; kt++) {
            float4 f0 = *(const float4*)&batch[(((size_t)row0 * 3 + kt) * 128 + i * 4 + tig) * 128 + j * 4];
            float4 f1 = *(const float4*)&batch[(((size_t)row1 * 3 + kt) * 128 + i * 4 + tig) * 128 + j * 4];
            uint32_t ah0 = pack2b(f0.x, f0.y), ah2 = pack2b(f0.z, f0.w);
            uint32_t ah1 = pack2b(f1.x, f1.y), ah3 = pack2b(f1.z, f1.w);
            uint32_t al0 = lo_resb(ah0, f0.x, f0.y), al2 = lo_resb(ah2, f0.z, f0.w);
            uint32_t al1 = lo_resb(ah1, f1.x, f1.y), al3 = lo_resb(ah3, f1.z, f1.w);
#pragma unroll
            for (int nt = 0; nt < 4; nt++) {
                const uint4 q = *(const uint4*)&sw[(nt * 8 + gid) * S_X + kt * 16 + tig * 4];
                mma16b(acc[nt], ah0, ah1, ah2, ah3, q.x, q.y);
                mma16b(acc[nt], ah0, ah1, ah2, ah3, q.z, q.w);
                mma16b(acc[nt], al0, al1, al2, al3, q.x, q.y);
            }
        }
        float* gp = d_G + (size_t)u * TB * G4;
#pragma unroll
        for (int nt = 0; nt < 4; nt++) {
            float* p0 = gp + (size_t)row0 * G4 + gb + nt * 8 + tig * 2;
            float* p1 = gp + (size_t)row1 * G4 + gb + nt * 8 + tig * 2;
            *(float2*)p0 = make_float2(acc[nt][0], acc[nt][1]);
            *(float2*)p1 = make_float2(acc[nt][2], acc[nt][3]);
        }
    }
}

// ---------------- persistent fused 2D-LSTM kernel ----------------
extern __shared__ uint32_t smw[];

__global__ void __launch_bounds__(THREADS, 1)
lstm2d_k(const float* __restrict__ W_ih, const float* __restrict__ W_hh,
         float* __restrict__ out) {
    const int tid  = threadIdx.x;
    const int lane = tid & 31;
    const int w    = tid >> 5;
    const int rg   = w & 1;             // row group within CTA's 32 rows
    const int kh   = (w >> 1) & 1;      // K half
    const bool isseq = (w < 4);
    const int gid  = lane >> 2;
    const int tig  = lane & 3;
    const int bid  = blockIdx.x;
    const int j    = bid >> 1;          // gate-col block: cols gg*512 + 8j + c
    const int s    = bid & 1;           // batch half: rows [32s, 32s+32)
    const int nb   = j * 8;
    const int row0g = s * 32 + rg * 16 + gid;   // global batch rows this warp covers
    const int row1g = row0g + 8;
    const int lr   = rg * 16 + gid;             // CTA-local row (ring addressing)
    const int ktb  = kh * 16;

    // ---- both weight blocks -> smem fp16 pairs. region 0: W_hh; region 1: W_ih[:,48:560] ----
    for (int idx = tid; idx < 2 * 32 * 256; idx += THREADS) {
        const int region = idx >> 13;
        const int id2 = idx & 8191;
        const int cl = id2 >> 8, k0 = (id2 & 255) * 2;
        const int grow = (cl >> 3) * NCH + nb + (cl & 7);
        float w0, w1;
        if (region == 0) {
            w0 = W_hh[(size_t)grow * NCH + k0];
            w1 = W_hh[(size_t)grow * NCH + k0 + 1];
        } else {
            w0 = W_ih[(size_t)grow * K_IH + 48 + k0];
            w1 = W_ih[(size_t)grow * K_IH + 48 + k0 + 1];
        }
        int kt = k0 >> 4, r = k0 & 15;
        smw[region * OFF_WPRE + cl * S_W + kt * 8 + (r >> 2) * 2 + ((r >> 1) & 1)] = pack2h(w0, w1);
    }
    __syncthreads();

    if (isseq) {
        // ================= SEQ WARPS (w0-w3) =================
        const int n0 = nb + tig * 2;
        float cst[4] = {0.f, 0.f, 0.f, 0.f};
        float* red = (float*)(smw + OFF_RED);

        float ga[4][4];
        if (kh == 0) {      // prologue: ga = G0[0]
#pragma unroll
            for (int gg = 0; gg < 4; gg++) {
                float2 v0 = __ldcg((const float2*)(d_G + (size_t)row0g * G4 + gg * NCH + n0));
                float2 v1 = __ldcg((const float2*)(d_G + (size_t)row1g * G4 + gg * NCH + n0));
                ga[gg][0] = v0.x; ga[gg][1] = v0.y; ga[gg][2] = v1.x; ga[gg][3] = v1.y;
            }
        }

        for (int t = 0; t < TSTEPS; t++) {
            if (t > 0 && tid < 128) {   // one poller per flag (128 flags)
                while (ld_acq(&d_h_done[tid * FPAD]) < t - 1) {}
            }
            __syncthreads();            // barrier A (CTA-wide, incl. pre warps)

            float acc[4][4];
#pragma unroll
            for (int gg = 0; gg < 4; gg++) {
#pragma unroll
                for (int i = 0; i < 4; i++) acc[gg][i] = (kh == 0) ? ga[gg][i] : 0.f;
            }

            float rng[4][4];
            if (t > 0) {
                uint4 A0[16], A1[16];
                const uint4* pq0 = d_Hq + ((size_t)(t - 1) * TB + row0g) * 128 + ktb * 4 + tig;
                const uint4* pq1 = d_Hq + ((size_t)(t - 1) * TB + row1g) * 128 + ktb * 4 + tig;
#pragma unroll
                for (int kt = 0; kt < 16; kt++) { A0[kt] = pq0[kt * 4]; A1[kt] = pq1[kt * 4]; }
                if (kh == 0 && t >= 32) {    // prefetch ring[t] alongside A
                    const float* rp = d_R + ((size_t)bid * RSL + (t & (RSL - 1))) * 1024;
#pragma unroll
                    for (int gg = 0; gg < 4; gg++) {
                        float2 v0 = __ldcg((const float2*)&rp[lr * 32 + gg * 8 + tig * 2]);
                        float2 v1 = __ldcg((const float2*)&rp[(lr + 8) * 32 + gg * 8 + tig * 2]);
                        rng[gg][0] = v0.x; rng[gg][1] = v0.y; rng[gg][2] = v1.x; rng[gg][3] = v1.y;
                    }
                }
#pragma unroll
                for (int kt = 0; kt < 16; kt++) {
#pragma unroll
                    for (int gg = 0; gg < 4; gg++) {
                        const uint2 q = *(const uint2*)&smw[(gg * 8 + gid) * S_W + (ktb + kt) * 8 + tig * 2];
                        mma16h(acc[gg], A0[kt].x, A1[kt].x, A0[kt].y, A1[kt].y, q.x, q.y);
                        mma16h(acc[gg], A0[kt].z, A1[kt].z, A0[kt].w, A1[kt].w, q.x, q.y);
                    }
                }
            }
            if (kh == 0) {   // prefetch ga <- G0[t+1]
                const int tn = (t < TSTEPS - 1) ? t + 1 : TSTEPS - 1;
                const float* gp = d_G + (size_t)tn * TB * G4;
#pragma unroll
                for (int gg = 0; gg < 4; gg++) {
                    float2 v0 = __ldcg((const float2*)(gp + (size_t)row0g * G4 + gg * NCH + n0));
                    float2 v1 = __ldcg((const float2*)(gp + (size_t)row1g * G4 + gg * NCH + n0));
                    ga[gg][0] = v0.x; ga[gg][1] = v0.y; ga[gg][2] = v1.x; ga[gg][3] = v1.y;
                }
            }

            if (kh == 1) {
                float* rp = red + (rg * 32 + lane) * 20;
#pragma unroll
                for (int gg = 0; gg < 4; gg++)
                    *(float4*)(rp + gg * 4) = make_float4(acc[gg][0], acc[gg][1], acc[gg][2], acc[gg][3]);
            }
            asm volatile("bar.sync 4, 128;" ::: "memory");   // seq warps only

            if (kh == 0) {
                const float* rp = red + (rg * 32 + lane) * 20;
#pragma unroll
                for (int gg = 0; gg < 4; gg++) {
                    float4 v = *(const float4*)(rp + gg * 4);
                    acc[gg][0] += v.x; acc[gg][1] += v.y; acc[gg][2] += v.z; acc[gg][3] += v.w;
                }
                if (t >= 32) {
#pragma unroll
                    for (int gg = 0; gg < 4; gg++) {
#pragma unroll
                        for (int i = 0; i < 4; i++) acc[gg][i] += rng[gg][i];
                    }
                }

                // activations (i,f,g,o) + publish h
                uint32_t hp[2], lp[2];
#pragma unroll
                for (int half = 0; half < 2; half++) {
                    const int pA = half * 2, pB = half * 2 + 1;
                    const int bb = (half == 0) ? row0g : row1g;
                    float c0 = sigm(acc[1][pA]) * cst[pA] + sigm(acc[0][pA]) * tanh_f(acc[2][pA]);
                    float c1 = sigm(acc[1][pB]) * cst[pB] + sigm(acc[0][pB]) * tanh_f(acc[2][pB]);
                    cst[pA] = c0; cst[pB] = c1;
                    float h0 = sigm(acc[3][pA]) * tanh_f(c0);
                    float h1 = sigm(acc[3][pB]) * tanh_f(c1);
                    *(float2*)&out[(size_t)bb * HSTRIDE + (size_t)t * NCH + n0] = make_float2(h0, h1);
                    hp[half] = pack2h(h0, h1);
                    lp[half] = lo_resh(hp[half], h0, h1);
                }
                uint32_t hp0p = __shfl_xor_sync(0xffffffffu, hp[0], 1);
                uint32_t lp0p = __shfl_xor_sync(0xffffffffu, lp[0], 1);
                uint32_t hp1p = __shfl_xor_sync(0xffffffffu, hp[1], 1);
                uint32_t lp1p = __shfl_xor_sync(0xffffffffu, lp[1], 1);
                const int grp = (nb >> 2) + (tig >> 1);
                uint4 val; size_t rsel;
                if (tig & 1) { val = make_uint4(hp1p, hp[1], lp1p, lp[1]); rsel = row1g; }
                else         { val = make_uint4(hp[0], hp0p, lp[0], lp0p); rsel = row0g; }
                d_Hq[((size_t)t * TB + rsel) * 128 + grp] = val;

                asm volatile("bar.sync 3, 64;" ::: "memory"); // w0,w1 only
                if (tid == 0) st_rel(&d_h_done[bid * FPAD], t);
            }
        }
    } else {
        // ================= PRE WARPS (w4-w7): ring[it+31] = h_{it-1} @ W_ihh^T =================
        const uint32_t* smp = smw + OFF_WPRE;
        float* red2 = (float*)(smw + OFF_RED2);
        float pacc[4][4];   // deferred accumulators (computed at it, stored at it+1)

        for (int it = 0; it < TSTEPS; it++) {
            __syncthreads();            // barrier A

            const bool dostore = (it >= 2 && it <= 993);   // store ring[it+30] from pacc(it-1)
            const bool domma   = (it >= 1 && it <= 992);   // compute ring[it+31] into pacc

            if (dostore && kh == 1) {
                float* rp = red2 + (rg * 32 + lane) * 20;
#pragma unroll
                for (int gg = 0; gg < 4; gg++)
                    *(float4*)(rp + gg * 4) = make_float4(pacc[gg][0], pacc[gg][1], pacc[gg][2], pacc[gg][3]);
            }
            asm volatile("bar.sync 5, 128;" ::: "memory");  // pre warps only

            if (dostore && kh == 0) {
                const float* rp = red2 + (rg * 32 + lane) * 20;
                float* wp = d_R + ((size_t)bid * RSL + ((it + 30) & (RSL - 1))) * 1024;
#pragma unroll
                for (int gg = 0; gg < 4; gg++) {
                    float4 v = *(const float4*)(rp + gg * 4);
                    *(float2*)&wp[lr * 32 + gg * 8 + tig * 2] =
                        make_float2(pacc[gg][0] + v.x, pacc[gg][1] + v.y);
                    *(float2*)&wp[(lr + 8) * 32 + gg * 8 + tig * 2] =
                        make_float2(pacc[gg][2] + v.z, pacc[gg][3] + v.w);
                }
            }

            if (domma) {
#pragma unroll
                for (int gg = 0; gg < 4; gg++) {
                    pacc[gg][0] = 0.f; pacc[gg][1] = 0.f; pacc[gg][2] = 0.f; pacc[gg][3] = 0.f;
                }
                uint4 A0[16], A1[16];
                const uint4* pq0 = d_Hq + ((size_t)(it - 1) * TB + row0g) * 128 + ktb * 4 + tig;
                const uint4* pq1 = d_Hq + ((size_t)(it - 1) * TB + row1g) * 128 + ktb * 4 + tig;
#pragma unroll
                for (int kt = 0; kt < 16; kt++) { A0[kt] = pq0[kt * 4]; A1[kt] = pq1[kt * 4]; }
#pragma unroll
                for (int kt = 0; kt < 16; kt++) {
#pragma unroll
                    for (int gg = 0; gg < 4; gg++) {
                        const uint2 q = *(const uint2*)&smp[(gg * 8 + gid) * S_W + (ktb + kt) * 8 + tig * 2];
                        mma16h(pacc[gg], A0[kt].x, A1[kt].x, A0[kt].y, A1[kt].y, q.x, q.y);
                        mma16h(pacc[gg], A0[kt].z, A1[kt].z, A0[kt].w, A1[kt].w, q.x, q.y);
                    }
                }
            }
        }
    }
}

// ---------------- launch ----------------
extern "C" void kernel_launch(void* const* d_in, const int* in_sizes, int n_in,
                              void* d_out, int out_size) {
    const float* batch = (const float*)d_in[0];
    const float* W_ih  = (const float*)d_in[1];
    const float* W_hh  = (const float*)d_in[2];
    const float* b_ih  = (const float*)d_in[3];
    const float* b_hh  = (const float*)d_in[4];
    float* out = (float*)d_out;

    const int smem = SMEM_WORDS * 4;   // 84224 B
    cudaFuncSetAttribute(lstm2d_k, cudaFuncAttributeMaxDynamicSharedMemorySize, smem);

    init_k<<<16, 256>>>();
    xc_k<<<dim3(64, 16), 128>>>(batch, W_ih, b_ih, b_hh);
    lstm2d_k<<<NCTA, THREADS, smem>>>(W_ih, W_hh, out);
}

// round 13
// speedup vs baseline: 1.1029x; 1.1029x over previous
#include <cuda_runtime.h>
#include <cuda_bf16.h>
#include <cuda_fp16.h>
#include <cstdint>

// ---------------- problem constants ----------------
#define TB      64          // batch
#define NCH     512         // hidden cells
#define TSTEPS  1024        // SY*SX
#define G4      2048        // 4*NCH gate columns
#define K_IH    560         // 48 + NCH
#define NCTA    128         // CTA (j,s): j = gate-col block (64), s = batch half (2)
#define THREADS 256         // 8 warps: rg=w&1 (16-row group), kq=w>>1 (K quarter)
#define HSTRIDE ((size_t)TSTEPS * NCH)
#define S_W     264         // smem words/col, fp16 pairs (==8 mod 32 -> conflict-free LDS.64)
#define S_X     48          // xc_k smem words/col
#define FPAD    32          // ints per flag: one 128B line each
#define RSL     32          // CTA-private ring slots
#define OFF_WPRE (32 * S_W)         // word offset: W_ihh weights
#define OFF_RED  (64 * S_W)         // word offset: reduction scratch (3 quarters * 64 thr * 36)
#define SMEM_WORDS (OFF_RED + 3 * 64 * 36)

// ---------------- device scratch (static: allocation-free) ----------------
__device__ float d_G[(size_t)TSTEPS * TB * G4];        // xc_k output (x@W_ihx + bias), 512 MB
__device__ uint4 d_Hq[(size_t)TSTEPS * TB * 128];      // h fp16 {hi2,hi2,lo2,lo2} per 4 cells
__device__ float d_R[(size_t)NCTA * RSL * 1024];       // CTA-private look-ahead rings, 16 MB
__device__ int   d_h_done[NCTA * FPAD];

// ---------------- bf16 helpers (xc_k only) ----------------
__device__ __forceinline__ uint32_t pack2b(float e0, float e1) {
    uint32_t d;
    asm("cvt.rn.bf16x2.f32 %0, %1, %2;" : "=r"(d) : "f"(e1), "f"(e0));
    return d;
}
__device__ __forceinline__ uint32_t lo_resb(uint32_t hp, float e0, float e1) {
    float h0 = __uint_as_float(hp << 16);
    float h1 = __uint_as_float(hp & 0xFFFF0000u);
    return pack2b(e0 - h0, e1 - h1);
}
__device__ __forceinline__ void mma16b(float* c,
                                       uint32_t a0, uint32_t a1, uint32_t a2, uint32_t a3,
                                       uint32_t b0, uint32_t b1) {
    asm volatile(
        "mma.sync.aligned.m16n8k16.row.col.f32.bf16.bf16.f32 "
        "{%0,%1,%2,%3},{%4,%5,%6,%7},{%8,%9},{%0,%1,%2,%3};"
        : "+f"(c[0]), "+f"(c[1]), "+f"(c[2]), "+f"(c[3])
        : "r"(a0), "r"(a1), "r"(a2), "r"(a3), "r"(b0), "r"(b1));
}

// ---------------- fp16 helpers ----------------
__device__ __forceinline__ uint32_t pack2h(float e0, float e1) {
    uint32_t d;
    asm("cvt.rn.f16x2.f32 %0, %1, %2;" : "=r"(d) : "f"(e1), "f"(e0));
    return d;
}
__device__ __forceinline__ uint32_t lo_resh(uint32_t hp, float e0, float e1) {
    __half2 h = *reinterpret_cast<__half2*>(&hp);
    float h0 = __half2float(__low2half(h));
    float h1 = __half2float(__high2half(h));
    return pack2h(e0 - h0, e1 - h1);
}
__device__ __forceinline__ void mma16h(float* c,
                                       uint32_t a0, uint32_t a1, uint32_t a2, uint32_t a3,
                                       uint32_t b0, uint32_t b1) {
    asm volatile(
        "mma.sync.aligned.m16n8k16.row.col.f32.f16.f16.f32 "
        "{%0,%1,%2,%3},{%4,%5,%6,%7},{%8,%9},{%0,%1,%2,%3};"
        : "+f"(c[0]), "+f"(c[1]), "+f"(c[2]), "+f"(c[3])
        : "r"(a0), "r"(a1), "r"(a2), "r"(a3), "r"(b0), "r"(b1));
}

__device__ __forceinline__ int ld_acq(const int* p) {
    int v;
    asm volatile("ld.acquire.gpu.global.b32 %0, [%1];" : "=r"(v) : "l"(p) : "memory");
    return v;
}
__device__ __forceinline__ void st_rel(int* p, int v) {
    asm volatile("st.release.gpu.global.b32 [%0], %1;" :: "l"(p), "r"(v) : "memory");
}
__device__ __forceinline__ uint4 ldcg4(const uint4* p) {
    uint4 v;
    asm volatile("ld.global.cg.v4.b32 {%0,%1,%2,%3}, [%4];"
                 : "=r"(v.x), "=r"(v.y), "=r"(v.z), "=r"(v.w) : "l"(p));
    return v;
}
__device__ __forceinline__ float sigm(float x)  { return 1.0f / (1.0f + __expf(-x)); }
__device__ __forceinline__ float tanh_f(float x){ return 1.0f - 2.0f / (__expf(2.0f * x) + 1.0f); }

// ---------------- init (graph-replay safe) ----------------
__global__ void init_k() {
    int i = blockIdx.x * blockDim.x + threadIdx.x;
    if (i < NCTA * FPAD) d_h_done[i] = -1;
}

// ---------------- Xc precompute: G0[t] = bias + x_t @ W_ih[:, :48]^T ----------------
__global__ void __launch_bounds__(128)
xc_k(const float* __restrict__ batch, const float* __restrict__ W_ih,
     const float* __restrict__ b_ih, const float* __restrict__ b_hh) {
    __shared__ uint32_t sw[32 * S_X];
    const int tid = threadIdx.x;
    const int lane = tid & 31, w = tid >> 5;
    const int gid = lane >> 2, tig = lane & 3;
    const int row0 = w * 16 + gid, row1 = row0 + 8;
    const int gb = blockIdx.x * 32;

    for (int idx = tid; idx < 32 * 24; idx += 128) {
        int cl = idx / 24, k0 = (idx - cl * 24) * 2;
        float w0 = W_ih[(size_t)(gb + cl) * K_IH + k0];
        float w1 = W_ih[(size_t)(gb + cl) * K_IH + k0 + 1];
        uint32_t hi = pack2b(w0, w1);
        int kt = k0 >> 4, r = k0 & 15;
        int pos = cl * S_X + kt * 16 + (r >> 2) * 4 + ((r >> 1) & 1);
        sw[pos] = hi; sw[pos + 2] = lo_resb(hi, w0, w1);
    }
    __syncthreads();

    float bias[4][2];
#pragma unroll
    for (int nt = 0; nt < 4; nt++) {
        int g = gb + nt * 8 + tig * 2;
        bias[nt][0] = b_ih[g] + b_hh[g];
        bias[nt][1] = b_ih[g + 1] + b_hh[g + 1];
    }

    for (int us = 0; us < 64; us++) {
        const int u = blockIdx.y * 64 + us;
        const int i = u >> 5, j = u & 31;
        float acc[4][4];
#pragma unroll
        for (int nt = 0; nt < 4; nt++) {
            acc[nt][0] = bias[nt][0]; acc[nt][1] = bias[nt][1];
            acc[nt][2] = bias[nt][0]; acc[nt][3] = bias[nt][1];
        }
#pragma unroll
        for (int kt = 0; kt < 3; kt++) {
            float4 f0 = *(const float4*)&batch[(((size_t)row0 * 3 + kt) * 128 + i * 4 + tig) * 128 + j * 4];
            float4 f1 = *(const float4*)&batch[(((size_t)row1 * 3 + kt) * 128 + i * 4 + tig) * 128 + j * 4];
            uint32_t ah0 = pack2b(f0.x, f0.y), ah2 = pack2b(f0.z, f0.w);
            uint32_t ah1 = pack2b(f1.x, f1.y), ah3 = pack2b(f1.z, f1.w);
            uint32_t al0 = lo_resb(ah0, f0.x, f0.y), al2 = lo_resb(ah2, f0.z, f0.w);
            uint32_t al1 = lo_resb(ah1, f1.x, f1.y), al3 = lo_resb(ah3, f1.z, f1.w);
#pragma unroll
            for (int nt = 0; nt < 4; nt++) {
                const uint4 q = *(const uint4*)&sw[(nt * 8 + gid) * S_X + kt * 16 + tig * 4];
                mma16b(acc[nt], ah0, ah1, ah2, ah3, q.x, q.y);
                mma16b(acc[nt], ah0, ah1, ah2, ah3, q.z, q.w);
                mma16b(acc[nt], al0, al1, al2, al3, q.x, q.y);
            }
        }
        float* gp = d_G + (size_t)u * TB * G4;
#pragma unroll
        for (int nt = 0; nt < 4; nt++) {
            float* p0 = gp + (size_t)row0 * G4 + gb + nt * 8 + tig * 2;
            float* p1 = gp + (size_t)row1 * G4 + gb + nt * 8 + tig * 2;
            *(float2*)p0 = make_float2(acc[nt][0], acc[nt][1]);
            *(float2*)p1 = make_float2(acc[nt][2], acc[nt][3]);
        }
    }
}

// ---------------- persistent 2D-LSTM kernel: dual-GEMM per CTA ----------------
extern __shared__ uint32_t smw[];

__global__ void __launch_bounds__(THREADS, 1)
lstm2d_k(const float* __restrict__ W_ih, const float* __restrict__ W_hh,
         float* __restrict__ out) {
    const int tid  = threadIdx.x;
    const int lane = tid & 31;
    const int w    = tid >> 5;
    const int rg   = w & 1;             // 16-row group within CTA's 32 rows
    const int kq   = w >> 1;            // K quarter: kt [8kq, 8kq+8)
    const int gid  = lane >> 2;
    const int tig  = lane & 3;
    const int bid  = blockIdx.x;
    const int j    = bid >> 1;          // gate-col block: cols gg*512 + 8j + c
    const int s    = bid & 1;           // batch half: rows [32s, 32s+32)
    const int nb   = j * 8;
    const int n0   = nb + tig * 2;
    const int lr   = rg * 16 + gid;     // CTA-local row
    const int row0g = s * 32 + lr;      // global batch rows
    const int row1g = row0g + 8;
    const int ktb  = kq * 8;
    const int trg  = rg * 32 + lane;    // thread slot for reduction
    float* red = (float*)(smw + OFF_RED);

    // ---- weights -> smem fp16 pairs. region 0: W_hh; region 1: W_ih[:,48:560] ----
    for (int idx = tid; idx < 2 * 32 * 256; idx += THREADS) {
        const int region = idx >> 13;
        const int id2 = idx & 8191;
        const int cl = id2 >> 8, k0 = (id2 & 255) * 2;
        const int grow = (cl >> 3) * NCH + nb + (cl & 7);
        float w0, w1;
        if (region == 0) {
            w0 = W_hh[(size_t)grow * NCH + k0];
            w1 = W_hh[(size_t)grow * NCH + k0 + 1];
        } else {
            w0 = W_ih[(size_t)grow * K_IH + 48 + k0];
            w1 = W_ih[(size_t)grow * K_IH + 48 + k0 + 1];
        }
        int kt = k0 >> 4, r = k0 & 15;
        smw[region * OFF_WPRE + cl * S_W + kt * 8 + (r >> 2) * 2 + ((r >> 1) & 1)] = pack2h(w0, w1);
    }
    __syncthreads();

    float cst[4] = {0.f, 0.f, 0.f, 0.f};

    float ga[4][4];
    if (kq == 0) {      // prologue: ga = G0[0]
#pragma unroll
        for (int gg = 0; gg < 4; gg++) {
            float2 v0 = __ldcg((const float2*)(d_G + (size_t)row0g * G4 + gg * NCH + n0));
            float2 v1 = __ldcg((const float2*)(d_G + (size_t)row1g * G4 + gg * NCH + n0));
            ga[gg][0] = v0.x; ga[gg][1] = v0.y; ga[gg][2] = v1.x; ga[gg][3] = v1.y;
        }
    }

    for (int t = 0; t < TSTEPS; t++) {
        if (t > 0 && tid < 128) {       // one poller per flag
            while (ld_acq(&d_h_done[tid * FPAD]) < t - 1) {}
        }
        __syncthreads();                // barrier A

        float ahh[4][4], aih[4][4];
#pragma unroll
        for (int gg = 0; gg < 4; gg++) {
#pragma unroll
            for (int i = 0; i < 4; i++) {
                ahh[gg][i] = (kq == 0) ? ga[gg][i] : 0.f;
                aih[gg][i] = 0.f;
            }
        }

        float rng[4][4];
        if (t > 0) {
            // front-batched A loads: 8 kt x 2 rows
            uint4 A0[8], A1[8];
            const uint4* pq0 = d_Hq + ((size_t)(t - 1) * TB + row0g) * 128 + ktb * 4 + tig;
            const uint4* pq1 = d_Hq + ((size_t)(t - 1) * TB + row1g) * 128 + ktb * 4 + tig;
#pragma unroll
            for (int kt = 0; kt < 8; kt++) { A0[kt] = ldcg4(pq0 + kt * 4); A1[kt] = ldcg4(pq1 + kt * 4); }
            if (kq == 0 && t >= 32) {   // prefetch ring[t] (written by this CTA at t-31)
                const float* rp = d_R + ((size_t)bid * RSL + (t & (RSL - 1))) * 1024;
#pragma unroll
                for (int gg = 0; gg < 4; gg++) {
                    float2 v0 = __ldcg((const float2*)&rp[lr * 32 + gg * 8 + tig * 2]);
                    float2 v1 = __ldcg((const float2*)&rp[(lr + 8) * 32 + gg * 8 + tig * 2]);
                    rng[gg][0] = v0.x; rng[gg][1] = v0.y; rng[gg][2] = v1.x; rng[gg][3] = v1.y;
                }
            }
            // dual mma: same A, two weight sets
#pragma unroll
            for (int kt = 0; kt < 8; kt++) {
#pragma unroll
                for (int gg = 0; gg < 4; gg++) {
                    const int wof = (gg * 8 + gid) * S_W + (ktb + kt) * 8 + tig * 2;
                    const uint2 qh = *(const uint2*)&smw[wof];
                    const uint2 qi = *(const uint2*)&smw[OFF_WPRE + wof];
                    mma16h(ahh[gg], A0[kt].x, A1[kt].x, A0[kt].y, A1[kt].y, qh.x, qh.y);
                    mma16h(ahh[gg], A0[kt].z, A1[kt].z, A0[kt].w, A1[kt].w, qh.x, qh.y);
                    mma16h(aih[gg], A0[kt].x, A1[kt].x, A0[kt].y, A1[kt].y, qi.x, qi.y);
                    mma16h(aih[gg], A0[kt].z, A1[kt].z, A0[kt].w, A1[kt].w, qi.x, qi.y);
                }
            }
        }
        if (kq == 0) {   // prefetch ga <- G0[t+1]
            const int tn = (t < TSTEPS - 1) ? t + 1 : TSTEPS - 1;
            const float* gp = d_G + (size_t)tn * TB * G4;
#pragma unroll
            for (int gg = 0; gg < 4; gg++) {
                float2 v0 = __ldcg((const float2*)(gp + (size_t)row0g * G4 + gg * NCH + n0));
                float2 v1 = __ldcg((const float2*)(gp + (size_t)row1g * G4 + gg * NCH + n0));
                ga[gg][0] = v0.x; ga[gg][1] = v0.y; ga[gg][2] = v1.x; ga[gg][3] = v1.y;
            }
        }

        // 4-quarter reduction (both accumulator sets)
        if (kq != 0) {
            float* rp = red + ((kq - 1) * 64 + trg) * 36;
#pragma unroll
            for (int gg = 0; gg < 4; gg++) {
                *(float4*)(rp + gg * 4)      = make_float4(ahh[gg][0], ahh[gg][1], ahh[gg][2], ahh[gg][3]);
                *(float4*)(rp + 16 + gg * 4) = make_float4(aih[gg][0], aih[gg][1], aih[gg][2], aih[gg][3]);
            }
        }
        __syncthreads();                // barrier B

        if (kq == 0) {
#pragma unroll
            for (int q = 1; q < 4; q++) {
                const float* rp = red + ((q - 1) * 64 + trg) * 36;
#pragma unroll
                for (int gg = 0; gg < 4; gg++) {
                    float4 vh = *(const float4*)(rp + gg * 4);
                    float4 vi = *(const float4*)(rp + 16 + gg * 4);
                    ahh[gg][0] += vh.x; ahh[gg][1] += vh.y; ahh[gg][2] += vh.z; ahh[gg][3] += vh.w;
                    aih[gg][0] += vi.x; aih[gg][1] += vi.y; aih[gg][2] += vi.z; aih[gg][3] += vi.w;
                }
            }
            if (t >= 32) {
#pragma unroll
                for (int gg = 0; gg < 4; gg++) {
#pragma unroll
                    for (int i = 0; i < 4; i++) ahh[gg][i] += rng[gg][i];
                }
            }

            // activations (i,f,g,o) + publish h
            uint32_t hp[2], lp[2];
#pragma unroll
            for (int half = 0; half < 2; half++) {
                const int pA = half * 2, pB = half * 2 + 1;
                const int bb = (half == 0) ? row0g : row1g;
                float c0 = sigm(ahh[1][pA]) * cst[pA] + sigm(ahh[0][pA]) * tanh_f(ahh[2][pA]);
                float c1 = sigm(ahh[1][pB]) * cst[pB] + sigm(ahh[0][pB]) * tanh_f(ahh[2][pB]);
                cst[pA] = c0; cst[pB] = c1;
                float h0 = sigm(ahh[3][pA]) * tanh_f(c0);
                float h1 = sigm(ahh[3][pB]) * tanh_f(c1);
                *(float2*)&out[(size_t)bb * HSTRIDE + (size_t)t * NCH + n0] = make_float2(h0, h1);
                hp[half] = pack2h(h0, h1);
                lp[half] = lo_resh(hp[half], h0, h1);
            }
            uint32_t hp0p = __shfl_xor_sync(0xffffffffu, hp[0], 1);
            uint32_t lp0p = __shfl_xor_sync(0xffffffffu, lp[0], 1);
            uint32_t hp1p = __shfl_xor_sync(0xffffffffu, hp[1], 1);
            uint32_t lp1p = __shfl_xor_sync(0xffffffffu, lp[1], 1);
            const int grp = (nb >> 2) + (tig >> 1);
            uint4 val; size_t rsel;
            if (tig & 1) { val = make_uint4(hp1p, hp[1], lp1p, lp[1]); rsel = row1g; }
            else         { val = make_uint4(hp[0], hp0p, lp[0], lp0p); rsel = row0g; }
            d_Hq[((size_t)t * TB + rsel) * 128 + grp] = val;

            // store look-ahead term P(t) = W_ihh . h(t-1) for step t+31
            if (t > 0) {
                float* wp = d_R + ((size_t)bid * RSL + ((t + 31) & (RSL - 1))) * 1024;
#pragma unroll
                for (int gg = 0; gg < 4; gg++) {
                    *(float2*)&wp[lr * 32 + gg * 8 + tig * 2]       = make_float2(aih[gg][0], aih[gg][1]);
                    *(float2*)&wp[(lr + 8) * 32 + gg * 8 + tig * 2] = make_float2(aih[gg][2], aih[gg][3]);
                }
            }

            asm volatile("bar.sync 3, 64;" ::: "memory");   // both kq0 warps
            if (tid == 0) st_rel(&d_h_done[bid * FPAD], t);
        }
    }
}

// ---------------- launch ----------------
extern "C" void kernel_launch(void* const* d_in, const int* in_sizes, int n_in,
                              void* d_out, int out_size) {
    const float* batch = (const float*)d_in[0];
    const float* W_ih  = (const float*)d_in[1];
    const float* W_hh  = (const float*)d_in[2];
    const float* b_ih  = (const float*)d_in[3];
    const float* b_hh  = (const float*)d_in[4];
    float* out = (float*)d_out;

    const int smem = SMEM_WORDS * 4;   // (16896 + 6912) * 4 = 95232 B
    cudaFuncSetAttribute(lstm2d_k, cudaFuncAttributeMaxDynamicSharedMemorySize, smem);

    init_k<<<16, 256>>>();
    xc_k<<<dim3(64, 16), 128>>>(batch, W_ih, b_ih, b_hh);
    lstm2d_k<<<NCTA, THREADS, smem>>>(W_ih, W_hh, out);
}

// round 14
// speedup vs baseline: 1.4542x; 1.3185x over previous
#include <cuda_runtime.h>
#include <cuda_bf16.h>
#include <cuda_fp16.h>
#include <cstdint>

// ---------------- problem constants ----------------
#define TB      64          // batch
#define NCH     512         // hidden cells
#define TSTEPS  1024        // SY*SX
#define G4      2048        // 4*NCH gate columns
#define K_IH    560         // 48 + NCH
#define NCTA    128         // CTA (j,s): j = gate-col block (64), s = batch half (2)
#define THREADS 256         // 8 warps: rg=w&1 (16-row group), kq=w>>1 (K quarter)
#define HSTRIDE ((size_t)TSTEPS * NCH)
#define S_W     264         // smem words/col, fp16 pairs (==8 mod 32 -> conflict-free LDS.64)
#define S_X     48          // xc_k smem words/col
#define FPAD    32          // ints per flag: one 128B line each
#define RSL     32          // CTA-private ring slots
#define OFF_WPRE (32 * S_W)         // word offset: W_ihh weights
#define OFF_RED  (64 * S_W)         // word offset: partials (2 sets x 4096 floats)
#define SMEM_WORDS (OFF_RED + 8192)

// ---------------- device scratch (static: allocation-free) ----------------
__device__ float d_G[(size_t)TSTEPS * TB * G4];        // xc_k output (x@W_ihx + bias), 512 MB
__device__ uint4 d_Hq[(size_t)TSTEPS * TB * 128];      // h fp16 {hi2,hi2,lo2,lo2} per 4 cells
__device__ float d_R[(size_t)NCTA * RSL * 1024];       // CTA-private look-ahead rings, 16 MB
__device__ int   d_h_done[NCTA * FPAD];                // flag (s*64 + j)

// ---------------- bf16 helpers (xc_k only) ----------------
__device__ __forceinline__ uint32_t pack2b(float e0, float e1) {
    uint32_t d;
    asm("cvt.rn.bf16x2.f32 %0, %1, %2;" : "=r"(d) : "f"(e1), "f"(e0));
    return d;
}
__device__ __forceinline__ uint32_t lo_resb(uint32_t hp, float e0, float e1) {
    float h0 = __uint_as_float(hp << 16);
    float h1 = __uint_as_float(hp & 0xFFFF0000u);
    return pack2b(e0 - h0, e1 - h1);
}
__device__ __forceinline__ void mma16b(float* c,
                                       uint32_t a0, uint32_t a1, uint32_t a2, uint32_t a3,
                                       uint32_t b0, uint32_t b1) {
    asm volatile(
        "mma.sync.aligned.m16n8k16.row.col.f32.bf16.bf16.f32 "
        "{%0,%1,%2,%3},{%4,%5,%6,%7},{%8,%9},{%0,%1,%2,%3};"
        : "+f"(c[0]), "+f"(c[1]), "+f"(c[2]), "+f"(c[3])
        : "r"(a0), "r"(a1), "r"(a2), "r"(a3), "r"(b0), "r"(b1));
}

// ---------------- fp16 helpers ----------------
__device__ __forceinline__ uint32_t pack2h(float e0, float e1) {
    uint32_t d;
    asm("cvt.rn.f16x2.f32 %0, %1, %2;" : "=r"(d) : "f"(e1), "f"(e0));
    return d;
}
__device__ __forceinline__ uint32_t lo_resh(uint32_t hp, float e0, float e1) {
    __half2 h = *reinterpret_cast<__half2*>(&hp);
    float h0 = __half2float(__low2half(h));
    float h1 = __half2float(__high2half(h));
    return pack2h(e0 - h0, e1 - h1);
}
__device__ __forceinline__ void mma16h(float* c,
                                       uint32_t a0, uint32_t a1, uint32_t a2, uint32_t a3,
                                       uint32_t b0, uint32_t b1) {
    asm volatile(
        "mma.sync.aligned.m16n8k16.row.col.f32.f16.f16.f32 "
        "{%0,%1,%2,%3},{%4,%5,%6,%7},{%8,%9},{%0,%1,%2,%3};"
        : "+f"(c[0]), "+f"(c[1]), "+f"(c[2]), "+f"(c[3])
        : "r"(a0), "r"(a1), "r"(a2), "r"(a3), "r"(b0), "r"(b1));
}

__device__ __forceinline__ int ld_acq(const int* p) {
    int v;
    asm volatile("ld.acquire.gpu.global.b32 %0, [%1];" : "=r"(v) : "l"(p) : "memory");
    return v;
}
__device__ __forceinline__ void st_rel(int* p, int v) {
    asm volatile("st.release.gpu.global.b32 [%0], %1;" :: "l"(p), "r"(v) : "memory");
}
__device__ __forceinline__ uint4 ldcg4(const uint4* p) {
    uint4 v;
    asm volatile("ld.global.cg.v4.b32 {%0,%1,%2,%3}, [%4];"
                 : "=r"(v.x), "=r"(v.y), "=r"(v.z), "=r"(v.w) : "l"(p));
    return v;
}
__device__ __forceinline__ float sigm(float x)  { return 1.0f / (1.0f + __expf(-x)); }
__device__ __forceinline__ float tanh_f(float x){ return 1.0f - 2.0f / (__expf(2.0f * x) + 1.0f); }

// ---------------- init (graph-replay safe) ----------------
__global__ void init_k() {
    int i = blockIdx.x * blockDim.x + threadIdx.x;
    if (i < NCTA * FPAD) d_h_done[i] = -1;
}

// ---------------- Xc precompute: G0[t] = bias + x_t @ W_ih[:, :48]^T ----------------
__global__ void __launch_bounds__(128)
xc_k(const float* __restrict__ batch, const float* __restrict__ W_ih,
     const float* __restrict__ b_ih, const float* __restrict__ b_hh) {
    __shared__ uint32_t sw[32 * S_X];
    const int tid = threadIdx.x;
    const int lane = tid & 31, w = tid >> 5;
    const int gid = lane >> 2, tig = lane & 3;
    const int row0 = w * 16 + gid, row1 = row0 + 8;
    const int gb = blockIdx.x * 32;

    for (int idx = tid; idx < 32 * 24; idx += 128) {
        int cl = idx / 24, k0 = (idx - cl * 24) * 2;
        float w0 = W_ih[(size_t)(gb + cl) * K_IH + k0];
        float w1 = W_ih[(size_t)(gb + cl) * K_IH + k0 + 1];
        uint32_t hi = pack2b(w0, w1);
        int kt = k0 >> 4, r = k0 & 15;
        int pos = cl * S_X + kt * 16 + (r >> 2) * 4 + ((r >> 1) & 1);
        sw[pos] = hi; sw[pos + 2] = lo_resb(hi, w0, w1);
    }
    __syncthreads();

    float bias[4][2];
#pragma unroll
    for (int nt = 0; nt < 4; nt++) {
        int g = gb + nt * 8 + tig * 2;
        bias[nt][0] = b_ih[g] + b_hh[g];
        bias[nt][1] = b_ih[g + 1] + b_hh[g + 1];
    }

    for (int us = 0; us < 64; us++) {
        const int u = blockIdx.y * 64 + us;
        const int i = u >> 5, j = u & 31;
        float acc[4][4];
#pragma unroll
        for (int nt = 0; nt < 4; nt++) {
            acc[nt][0] = bias[nt][0]; acc[nt][1] = bias[nt][1];
            acc[nt][2] = bias[nt][0]; acc[nt][3] = bias[nt][1];
        }
#pragma unroll
        for (int kt = 0; kt < 3; kt++) {
            float4 f0 = *(const float4*)&batch[(((size_t)row0 * 3 + kt) * 128 + i * 4 + tig) * 128 + j * 4];
            float4 f1 = *(const float4*)&batch[(((size_t)row1 * 3 + kt) * 128 + i * 4 + tig) * 128 + j * 4];
            uint32_t ah0 = pack2b(f0.x, f0.y), ah2 = pack2b(f0.z, f0.w);
            uint32_t ah1 = pack2b(f1.x, f1.y), ah3 = pack2b(f1.z, f1.w);
            uint32_t al0 = lo_resb(ah0, f0.x, f0.y), al2 = lo_resb(ah2, f0.z, f0.w);
            uint32_t al1 = lo_resb(ah1, f1.x, f1.y), al3 = lo_resb(ah3, f1.z, f1.w);
#pragma unroll
            for (int nt = 0; nt < 4; nt++) {
                const uint4 q = *(const uint4*)&sw[(nt * 8 + gid) * S_X + kt * 16 + tig * 4];
                mma16b(acc[nt], ah0, ah1, ah2, ah3, q.x, q.y);
                mma16b(acc[nt], ah0, ah1, ah2, ah3, q.z, q.w);
                mma16b(acc[nt], al0, al1, al2, al3, q.x, q.y);
            }
        }
        float* gp = d_G + (size_t)u * TB * G4;
#pragma unroll
        for (int nt = 0; nt < 4; nt++) {
            float* p0 = gp + (size_t)row0 * G4 + gb + nt * 8 + tig * 2;
            float* p1 = gp + (size_t)row1 * G4 + gb + nt * 8 + tig * 2;
            *(float2*)p0 = make_float2(acc[nt][0], acc[nt][1]);
            *(float2*)p1 = make_float2(acc[nt][2], acc[nt][3]);
        }
    }
}

// ---------------- persistent 2D-LSTM kernel: dual-GEMM + parallel epilogue ----------------
extern __shared__ uint32_t smw[];

__global__ void __launch_bounds__(THREADS, 1)
lstm2d_k(const float* __restrict__ W_ih, const float* __restrict__ W_hh,
         float* __restrict__ out) {
    const int tid  = threadIdx.x;
    const int lane = tid & 31;
    const int w    = tid >> 5;
    const int rg   = w & 1;             // 16-row group (producer role)
    const int kq   = w >> 1;            // K quarter: kt [8kq, 8kq+8)
    const int gid  = lane >> 2;
    const int tig  = lane & 3;
    const int bid  = blockIdx.x;
    const int j    = bid >> 1;          // gate-col block: cols gg*512 + 8j + c
    const int s    = bid & 1;           // batch half: rows [32s, 32s+32)
    const int nb   = j * 8;
    const int prow0 = s * 32 + rg * 16 + gid;   // producer rows
    const int prow1 = prow0 + 8;
    const int ktb  = kq * 8;
    // consumer (epilogue) mapping: one (row, col) cell per thread
    const int crow = tid >> 3;          // 0..31 CTA-local row
    const int ccol = tid & 7;           // 0..7 local n
    const int grow = s * 32 + crow;     // global batch row
    float* red  = (float*)(smw + OFF_RED);          // hh partials: [kq*4+gg][32][8]
    float* red2 = red + 4096;                        // ih partials

    // ---- weights -> smem fp16 pairs. region 0: W_hh; region 1: W_ih[:,48:560] ----
    for (int idx = tid; idx < 2 * 32 * 256; idx += THREADS) {
        const int region = idx >> 13;
        const int id2 = idx & 8191;
        const int cl = id2 >> 8, k0 = (id2 & 255) * 2;
        const int growt = (cl >> 3) * NCH + nb + (cl & 7);
        float w0, w1;
        if (region == 0) {
            w0 = W_hh[(size_t)growt * NCH + k0];
            w1 = W_hh[(size_t)growt * NCH + k0 + 1];
        } else {
            w0 = W_ih[(size_t)growt * K_IH + 48 + k0];
            w1 = W_ih[(size_t)growt * K_IH + 48 + k0 + 1];
        }
        int kt = k0 >> 4, r = k0 & 15;
        smw[region * OFF_WPRE + cl * S_W + kt * 8 + (r >> 2) * 2 + ((r >> 1) & 1)] = pack2h(w0, w1);
    }
    __syncthreads();

    float cst = 0.f;        // per-thread cell state for (grow, nb+ccol)
    float ga[4];            // per-thread G0 prefetch
#pragma unroll
    for (int gg = 0; gg < 4; gg++)
        ga[gg] = __ldcg(&d_G[(size_t)grow * G4 + gg * NCH + nb + ccol]);

    for (int t = 0; t < TSTEPS; t++) {
        // poll: only own-half flags (64 producers)
        if (t > 0 && tid < 64) {
            while (ld_acq(&d_h_done[(s * 64 + tid) * FPAD]) < t - 1) {}
        }
        __syncthreads();                // barrier A

        // early ring read (slot t, written by this CTA at t-31)
        float rngv[4] = {0.f, 0.f, 0.f, 0.f};
        if (t >= 32) {
            const float* rp = d_R + ((size_t)bid * RSL + (t & (RSL - 1))) * 1024;
#pragma unroll
            for (int gg = 0; gg < 4; gg++) rngv[gg] = __ldcg(&rp[(gg * 32 + crow) * 8 + ccol]);
        }

        if (t > 0) {
            float ahh[4][4], aih[4][4];
#pragma unroll
            for (int gg = 0; gg < 4; gg++)
#pragma unroll
                for (int i = 0; i < 4; i++) { ahh[gg][i] = 0.f; aih[gg][i] = 0.f; }

            // front-batched A loads: 8 kt x 2 rows
            uint4 A0[8], A1[8];
            const uint4* pq0 = d_Hq + ((size_t)(t - 1) * TB + prow0) * 128 + ktb * 4 + tig;
            const uint4* pq1 = d_Hq + ((size_t)(t - 1) * TB + prow1) * 128 + ktb * 4 + tig;
#pragma unroll
            for (int kt = 0; kt < 8; kt++) { A0[kt] = ldcg4(pq0 + kt * 4); A1[kt] = ldcg4(pq1 + kt * 4); }
            // dual mma: same A, two weight sets
#pragma unroll
            for (int kt = 0; kt < 8; kt++) {
#pragma unroll
                for (int gg = 0; gg < 4; gg++) {
                    const int wof = (gg * 8 + gid) * S_W + (ktb + kt) * 8 + tig * 2;
                    const uint2 qh = *(const uint2*)&smw[wof];
                    const uint2 qi = *(const uint2*)&smw[OFF_WPRE + wof];
                    mma16h(ahh[gg], A0[kt].x, A1[kt].x, A0[kt].y, A1[kt].y, qh.x, qh.y);
                    mma16h(ahh[gg], A0[kt].z, A1[kt].z, A0[kt].w, A1[kt].w, qh.x, qh.y);
                    mma16h(aih[gg], A0[kt].x, A1[kt].x, A0[kt].y, A1[kt].y, qi.x, qi.y);
                    mma16h(aih[gg], A0[kt].z, A1[kt].z, A0[kt].w, A1[kt].w, qi.x, qi.y);
                }
            }

            // write partials: [kq*4+gg][lrow][col] (float2 over col pair)
#pragma unroll
            for (int gg = 0; gg < 4; gg++) {
                const int base = ((kq * 4 + gg) * 32 + (rg * 16 + gid)) * 8 + tig * 2;
                *(float2*)&red[base]         = make_float2(ahh[gg][0], ahh[gg][1]);
                *(float2*)&red[base + 64]    = make_float2(ahh[gg][2], ahh[gg][3]);
                *(float2*)&red2[base]        = make_float2(aih[gg][0], aih[gg][1]);
                *(float2*)&red2[base + 64]   = make_float2(aih[gg][2], aih[gg][3]);
            }
        }
        __syncthreads();                // barrier B

        // ---- parallel epilogue: each thread owns (crow, ccol) ----
        float sumh[4], sumi[4];
#pragma unroll
        for (int gg = 0; gg < 4; gg++) { sumh[gg] = ga[gg]; sumi[gg] = 0.f; }
        if (t > 0) {
#pragma unroll
            for (int q = 0; q < 4; q++) {
#pragma unroll
                for (int gg = 0; gg < 4; gg++) {
                    const int a = ((q * 4 + gg) * 32 + crow) * 8 + ccol;
                    sumh[gg] += red[a];
                    sumi[gg] += red2[a];
                }
            }
        }
        if (t >= 32) {
#pragma unroll
            for (int gg = 0; gg < 4; gg++) sumh[gg] += rngv[gg];
        }

        // activations (i,f,g,o)
        float cc = sigm(sumh[1]) * cst + sigm(sumh[0]) * tanh_f(sumh[2]);
        cst = cc;
        float h = sigm(sumh[3]) * tanh_f(cc);

        // pack + publish d_Hq (only piece needed before release)
        {
            float a = __shfl_xor_sync(0xffffffffu, h, 1);
            float e0 = (ccol & 1) ? a : h;
            float e1 = (ccol & 1) ? h : a;
            uint32_t hpair = pack2h(e0, e1);
            uint32_t lpair = lo_resh(hpair, e0, e1);
            uint32_t hpair2 = __shfl_xor_sync(0xffffffffu, hpair, 2);
            uint32_t lpair2 = __shfl_xor_sync(0xffffffffu, lpair, 2);
            if ((ccol & 3) == 0) {
                d_Hq[((size_t)t * TB + grow) * 128 + j * 2 + (ccol >> 2)] =
                    make_uint4(hpair, hpair2, lpair, lpair2);
            }
        }
        __syncthreads();                // barrier C: all d_Hq stores issued
        if (tid == 0) st_rel(&d_h_done[(s * 64 + j) * FPAD], t);

        // ---- off-critical-path: out store, ring store, G0 prefetch ----
        out[(size_t)grow * HSTRIDE + (size_t)t * NCH + nb + ccol] = h;
        if (t > 0) {
            float* wp = d_R + ((size_t)bid * RSL + ((t + 31) & (RSL - 1))) * 1024;
#pragma unroll
            for (int gg = 0; gg < 4; gg++) wp[(gg * 32 + crow) * 8 + ccol] = sumi[gg];
        }
        {
            const int tn = (t < TSTEPS - 1) ? t + 1 : TSTEPS - 1;
#pragma unroll
            for (int gg = 0; gg < 4; gg++)
                ga[gg] = __ldcg(&d_G[((size_t)tn * TB + grow) * G4 + gg * NCH + nb + ccol]);
        }
    }
}

// ---------------- launch ----------------
extern "C" void kernel_launch(void* const* d_in, const int* in_sizes, int n_in,
                              void* d_out, int out_size) {
    const float* batch = (const float*)d_in[0];
    const float* W_ih  = (const float*)d_in[1];
    const float* W_hh  = (const float*)d_in[2];
    const float* b_ih  = (const float*)d_in[3];
    const float* b_hh  = (const float*)d_in[4];
    float* out = (float*)d_out;

    const int smem = SMEM_WORDS * 4;   // (16896 + 8192) * 4 = 100352 B
    cudaFuncSetAttribute(lstm2d_k, cudaFuncAttributeMaxDynamicSharedMemorySize, smem);

    init_k<<<16, 256>>>();
    xc_k<<<dim3(64, 16), 128>>>(batch, W_ih, b_ih, b_hh);
    lstm2d_k<<<NCTA, THREADS, smem>>>(W_ih, W_hh, out);
}